// round 5
// baseline (speedup 1.0000x reference)
#include <cuda_runtime.h>
#include <cstdint>

#define N_NODES 100000
#define N_EDGES 625000
#define EMB     128
#define SCALE   0.4f   // alpha/2
#define CAP     64     // max slots per row; Poisson(6.25) max over 100k rows ~30

// Device scratch (allocation-free rule: __device__ globals).
// g_count is zero-initialized at module load; gather_kernel resets it to 0
// after consuming it, so every kernel_launch call enters with counts == 0.
__device__ int    g_count[N_NODES];               // degree histogram == alloc cursor
__device__ float2 g_edge[(size_t)N_NODES * CAP];  // (col bits, val), 51.2 MB

// ---- 1. fused histogram + scatter into fixed-capacity buckets ----
// 4 edges per thread, vectorized meta loads. N_EDGES % 4 == 0.
__global__ void scatter_kernel(const float* __restrict__ vals,
                               const int*  __restrict__ rows,
                               const int*  __restrict__ cols) {
    int i = (blockIdx.x * blockDim.x + threadIdx.x) * 4;
    if (i >= N_EDGES) return;
    int4   r4 = *reinterpret_cast<const int4*>(rows + i);
    int4   c4 = *reinterpret_cast<const int4*>(cols + i);
    float4 v4 = *reinterpret_cast<const float4*>(vals + i);

    int p0 = atomicAdd(&g_count[r4.x], 1);
    int p1 = atomicAdd(&g_count[r4.y], 1);
    int p2 = atomicAdd(&g_count[r4.z], 1);
    int p3 = atomicAdd(&g_count[r4.w], 1);
    if (p0 < CAP) g_edge[(size_t)r4.x * CAP + p0] = make_float2(__int_as_float(c4.x), v4.x);
    if (p1 < CAP) g_edge[(size_t)r4.y * CAP + p1] = make_float2(__int_as_float(c4.y), v4.y);
    if (p2 < CAP) g_edge[(size_t)r4.z * CAP + p2] = make_float2(__int_as_float(c4.z), v4.z);
    if (p3 < CAP) g_edge[(size_t)r4.w * CAP + p3] = make_float2(__int_as_float(c4.w), v4.w);
}

// ---- 2. gather: one warp per node, conflict-free, fuses init,
//         and self-cleans g_count for the next call ----
__global__ void __launch_bounds__(256) gather_kernel(
        const float* __restrict__ x,
        const float* __restrict__ emb,
        float* __restrict__ out) {
    int lane = threadIdx.x & 31;
    int n = (blockIdx.x * blockDim.x + threadIdx.x) >> 5;
    if (n >= N_NODES) return;

    int deg = g_count[n];
    // reset for next kernel_launch call (self-cleaning invariant)
    if (lane == 0) g_count[n] = 0;
    if (deg > CAP) deg = CAP;
    const float2* ebase = g_edge + (size_t)n * CAP;

    const float4* xr = reinterpret_cast<const float4*>(x   + (size_t)n * EMB) + lane;
    const float4* er = reinterpret_cast<const float4*>(emb + (size_t)n * EMB) + lane;
    float4 xv0 = *xr;
    float4 ev  = *er;
    float4 acc;
    acc.x = ev.x - xv0.x;
    acc.y = ev.y - xv0.y;
    acc.z = ev.z - xv0.z;
    acc.w = ev.w - xv0.w;

    int j = 0;
    // 4-way unrolled: four independent gathers in flight per warp
    for (; j + 3 < deg; j += 4) {
        float4 m01 = *reinterpret_cast<const float4*>(ebase + j);
        float4 m23 = *reinterpret_cast<const float4*>(ebase + j + 2);
        int   c0 = __float_as_int(m01.x), c1 = __float_as_int(m01.z);
        int   c2 = __float_as_int(m23.x), c3 = __float_as_int(m23.z);
        float v0 = m01.y * SCALE, v1 = m01.w * SCALE;
        float v2 = m23.y * SCALE, v3 = m23.w * SCALE;
        float4 a0 = *(reinterpret_cast<const float4*>(x + (size_t)c0 * EMB) + lane);
        float4 a1 = *(reinterpret_cast<const float4*>(x + (size_t)c1 * EMB) + lane);
        float4 a2 = *(reinterpret_cast<const float4*>(x + (size_t)c2 * EMB) + lane);
        float4 a3 = *(reinterpret_cast<const float4*>(x + (size_t)c3 * EMB) + lane);
        acc.x += v0 * a0.x; acc.y += v0 * a0.y; acc.z += v0 * a0.z; acc.w += v0 * a0.w;
        acc.x += v1 * a1.x; acc.y += v1 * a1.y; acc.z += v1 * a1.z; acc.w += v1 * a1.w;
        acc.x += v2 * a2.x; acc.y += v2 * a2.y; acc.z += v2 * a2.z; acc.w += v2 * a2.w;
        acc.x += v3 * a3.x; acc.y += v3 * a3.y; acc.z += v3 * a3.z; acc.w += v3 * a3.w;
    }
    for (; j + 1 < deg; j += 2) {
        float4 m01 = *reinterpret_cast<const float4*>(ebase + j);
        int   c0 = __float_as_int(m01.x), c1 = __float_as_int(m01.z);
        float v0 = m01.y * SCALE, v1 = m01.w * SCALE;
        float4 a0 = *(reinterpret_cast<const float4*>(x + (size_t)c0 * EMB) + lane);
        float4 a1 = *(reinterpret_cast<const float4*>(x + (size_t)c1 * EMB) + lane);
        acc.x += v0 * a0.x; acc.y += v0 * a0.y; acc.z += v0 * a0.z; acc.w += v0 * a0.w;
        acc.x += v1 * a1.x; acc.y += v1 * a1.y; acc.z += v1 * a1.z; acc.w += v1 * a1.w;
    }
    if (j < deg) {
        float2 e0 = ebase[j];
        int   c0 = __float_as_int(e0.x);
        float v0 = e0.y * SCALE;
        float4 a0 = *(reinterpret_cast<const float4*>(x + (size_t)c0 * EMB) + lane);
        acc.x += v0 * a0.x; acc.y += v0 * a0.y; acc.z += v0 * a0.z; acc.w += v0 * a0.w;
    }

    reinterpret_cast<float4*>(out + (size_t)n * EMB)[lane] = acc;
}

extern "C" void kernel_launch(void* const* d_in, const int* in_sizes, int n_in,
                              void* d_out, int out_size) {
    // metadata order: t, x, e, hg_vals, hg_rows, hg_cols
    const float* x    = (const float*)d_in[1];
    const float* emb  = (const float*)d_in[2];
    const float* vals = (const float*)d_in[3];
    const int*   rows = (const int*)d_in[4];
    const int*   cols = (const int*)d_in[5];
    float* out = (float*)d_out;

    scatter_kernel<<<(N_EDGES / 4 + 255) / 256, 256>>>(vals, rows, cols);
    gather_kernel<<<(N_NODES * 32 + 255) / 256, 256>>>(x, emb, out);
}

// round 6
// speedup vs baseline: 1.4195x; 1.4195x over previous
#include <cuda_runtime.h>
#include <cstdint>

#define N_NODES 100000
#define N_EDGES 625000
#define EMB     128
#define SCALE   0.4f   // alpha/2
#define CAP     64     // max slots per row; Poisson(6.25) max over 100k rows ~30

// Device scratch (allocation-free rule: __device__ globals)
__device__ int    g_count[N_NODES];               // degree histogram == alloc cursor
__device__ float2 g_edge[(size_t)N_NODES * CAP];  // (col bits, val)

// ---- 1. zero counters (vectorized; N_NODES % 4 == 0) ----
__global__ void zero_kernel() {
    int i = blockIdx.x * blockDim.x + threadIdx.x;
    if (i < N_NODES / 4) reinterpret_cast<int4*>(g_count)[i] = make_int4(0, 0, 0, 0);
}

// ---- 2. fused histogram + scatter into fixed-capacity buckets ----
// 4 edges per thread, vectorized meta loads. N_EDGES % 4 == 0.
__global__ void scatter_kernel(const float* __restrict__ vals,
                               const int*  __restrict__ rows,
                               const int*  __restrict__ cols) {
    int i = (blockIdx.x * blockDim.x + threadIdx.x) * 4;
    if (i >= N_EDGES) return;
    int4   r4 = __ldcs(reinterpret_cast<const int4*>(rows + i));
    int4   c4 = __ldcs(reinterpret_cast<const int4*>(cols + i));
    float4 v4 = __ldcs(reinterpret_cast<const float4*>(vals + i));

    int p0 = atomicAdd(&g_count[r4.x], 1);
    int p1 = atomicAdd(&g_count[r4.y], 1);
    int p2 = atomicAdd(&g_count[r4.z], 1);
    int p3 = atomicAdd(&g_count[r4.w], 1);
    if (p0 < CAP) g_edge[(size_t)r4.x * CAP + p0] = make_float2(__int_as_float(c4.x), v4.x);
    if (p1 < CAP) g_edge[(size_t)r4.y * CAP + p1] = make_float2(__int_as_float(c4.y), v4.y);
    if (p2 < CAP) g_edge[(size_t)r4.z * CAP + p2] = make_float2(__int_as_float(c4.z), v4.z);
    if (p3 < CAP) g_edge[(size_t)r4.w * CAP + p3] = make_float2(__int_as_float(c4.w), v4.w);
}

// ---- 3. gather: one warp per node, conflict-free, fuses init ----
// Streaming hints: e / out / edge-meta are touched once per call -> evict-first,
// keeping the randomly-gathered x (reused ~6.25x) resident in L2.
__global__ void __launch_bounds__(256) gather_kernel(
        const float* __restrict__ x,
        const float* __restrict__ emb,
        float* __restrict__ out) {
    int lane = threadIdx.x & 31;
    int n = (blockIdx.x * blockDim.x + threadIdx.x) >> 5;
    if (n >= N_NODES) return;

    int deg = g_count[n];
    if (deg > CAP) deg = CAP;
    const float2* ebase = g_edge + (size_t)n * CAP;

    const float4* xr = reinterpret_cast<const float4*>(x   + (size_t)n * EMB) + lane;
    const float4* er = reinterpret_cast<const float4*>(emb + (size_t)n * EMB) + lane;
    float4 xv0 = *xr;
    float4 ev  = __ldcs(er);
    float4 acc;
    acc.x = ev.x - xv0.x;
    acc.y = ev.y - xv0.y;
    acc.z = ev.z - xv0.z;
    acc.w = ev.w - xv0.w;

    int j = 0;
    // 4-way unrolled: four independent gathers in flight per warp
    for (; j + 3 < deg; j += 4) {
        float4 m01 = __ldcs(reinterpret_cast<const float4*>(ebase + j));
        float4 m23 = __ldcs(reinterpret_cast<const float4*>(ebase + j + 2));
        int   c0 = __float_as_int(m01.x), c1 = __float_as_int(m01.z);
        int   c2 = __float_as_int(m23.x), c3 = __float_as_int(m23.z);
        float v0 = m01.y * SCALE, v1 = m01.w * SCALE;
        float v2 = m23.y * SCALE, v3 = m23.w * SCALE;
        float4 a0 = *(reinterpret_cast<const float4*>(x + (size_t)c0 * EMB) + lane);
        float4 a1 = *(reinterpret_cast<const float4*>(x + (size_t)c1 * EMB) + lane);
        float4 a2 = *(reinterpret_cast<const float4*>(x + (size_t)c2 * EMB) + lane);
        float4 a3 = *(reinterpret_cast<const float4*>(x + (size_t)c3 * EMB) + lane);
        acc.x += v0 * a0.x; acc.y += v0 * a0.y; acc.z += v0 * a0.z; acc.w += v0 * a0.w;
        acc.x += v1 * a1.x; acc.y += v1 * a1.y; acc.z += v1 * a1.z; acc.w += v1 * a1.w;
        acc.x += v2 * a2.x; acc.y += v2 * a2.y; acc.z += v2 * a2.z; acc.w += v2 * a2.w;
        acc.x += v3 * a3.x; acc.y += v3 * a3.y; acc.z += v3 * a3.z; acc.w += v3 * a3.w;
    }
    for (; j + 1 < deg; j += 2) {
        float4 m01 = __ldcs(reinterpret_cast<const float4*>(ebase + j));
        int   c0 = __float_as_int(m01.x), c1 = __float_as_int(m01.z);
        float v0 = m01.y * SCALE, v1 = m01.w * SCALE;
        float4 a0 = *(reinterpret_cast<const float4*>(x + (size_t)c0 * EMB) + lane);
        float4 a1 = *(reinterpret_cast<const float4*>(x + (size_t)c1 * EMB) + lane);
        acc.x += v0 * a0.x; acc.y += v0 * a0.y; acc.z += v0 * a0.z; acc.w += v0 * a0.w;
        acc.x += v1 * a1.x; acc.y += v1 * a1.y; acc.z += v1 * a1.z; acc.w += v1 * a1.w;
    }
    if (j < deg) {
        float2 e0 = __ldcs(ebase + j);
        int   c0 = __float_as_int(e0.x);
        float v0 = e0.y * SCALE;
        float4 a0 = *(reinterpret_cast<const float4*>(x + (size_t)c0 * EMB) + lane);
        acc.x += v0 * a0.x; acc.y += v0 * a0.y; acc.z += v0 * a0.z; acc.w += v0 * a0.w;
    }

    __stcs(reinterpret_cast<float4*>(out + (size_t)n * EMB) + lane, acc);
}

extern "C" void kernel_launch(void* const* d_in, const int* in_sizes, int n_in,
                              void* d_out, int out_size) {
    // metadata order: t, x, e, hg_vals, hg_rows, hg_cols
    const float* x    = (const float*)d_in[1];
    const float* emb  = (const float*)d_in[2];
    const float* vals = (const float*)d_in[3];
    const int*   rows = (const int*)d_in[4];
    const int*   cols = (const int*)d_in[5];
    float* out = (float*)d_out;

    zero_kernel<<<(N_NODES / 4 + 255) / 256, 256>>>();
    scatter_kernel<<<(N_EDGES / 4 + 255) / 256, 256>>>(vals, rows, cols);
    gather_kernel<<<(N_NODES * 32 + 255) / 256, 256>>>(x, emb, out);
}

// round 8
// speedup vs baseline: 1.5702x; 1.1062x over previous
#include <cuda_runtime.h>
#include <cstdint>

#define N_NODES 100000
#define N_EDGES 625000
#define EMB     128
#define SCALE   0.4f   // alpha/2
#define CAP     64     // max slots per row; Poisson(6.25) max over 100k rows ~30

// Device scratch (allocation-free rule: __device__ globals)
__device__ int    g_count[N_NODES];               // degree histogram == alloc cursor
__device__ float2 g_edge[(size_t)N_NODES * CAP];  // (col bits, val)

// ---- 1. fused histogram + scatter into fixed-capacity buckets ----
// 4 edges per thread, vectorized meta loads. N_EDGES % 4 == 0.
__global__ void scatter_kernel(const float* __restrict__ vals,
                               const int*  __restrict__ rows,
                               const int*  __restrict__ cols) {
    int i = (blockIdx.x * blockDim.x + threadIdx.x) * 4;
    if (i >= N_EDGES) return;
    int4   r4 = *reinterpret_cast<const int4*>(rows + i);
    int4   c4 = *reinterpret_cast<const int4*>(cols + i);
    float4 v4 = *reinterpret_cast<const float4*>(vals + i);

    int p0 = atomicAdd(&g_count[r4.x], 1);
    int p1 = atomicAdd(&g_count[r4.y], 1);
    int p2 = atomicAdd(&g_count[r4.z], 1);
    int p3 = atomicAdd(&g_count[r4.w], 1);
    if (p0 < CAP) g_edge[(size_t)r4.x * CAP + p0] = make_float2(__int_as_float(c4.x), v4.x);
    if (p1 < CAP) g_edge[(size_t)r4.y * CAP + p1] = make_float2(__int_as_float(c4.y), v4.y);
    if (p2 < CAP) g_edge[(size_t)r4.z * CAP + p2] = make_float2(__int_as_float(c4.z), v4.z);
    if (p3 < CAP) g_edge[(size_t)r4.w * CAP + p3] = make_float2(__int_as_float(c4.w), v4.w);
}

// ---- 2. gather: one warp per node, conflict-free, fuses init ----
__global__ void __launch_bounds__(256) gather_kernel(
        const float* __restrict__ x,
        const float* __restrict__ emb,
        float* __restrict__ out) {
    int lane = threadIdx.x & 31;
    int n = (blockIdx.x * blockDim.x + threadIdx.x) >> 5;
    if (n >= N_NODES) return;

    int deg = g_count[n];
    if (deg > CAP) deg = CAP;
    const float2* ebase = g_edge + (size_t)n * CAP;

    const float4* xr = reinterpret_cast<const float4*>(x   + (size_t)n * EMB) + lane;
    const float4* er = reinterpret_cast<const float4*>(emb + (size_t)n * EMB) + lane;
    float4 xv0 = *xr;
    float4 ev  = *er;
    float4 acc;
    acc.x = ev.x - xv0.x;
    acc.y = ev.y - xv0.y;
    acc.z = ev.z - xv0.z;
    acc.w = ev.w - xv0.w;

    int j = 0;
    // 4-way unrolled: four independent gathers in flight per warp
    for (; j + 3 < deg; j += 4) {
        float4 m01 = *reinterpret_cast<const float4*>(ebase + j);
        float4 m23 = *reinterpret_cast<const float4*>(ebase + j + 2);
        int   c0 = __float_as_int(m01.x), c1 = __float_as_int(m01.z);
        int   c2 = __float_as_int(m23.x), c3 = __float_as_int(m23.z);
        float v0 = m01.y * SCALE, v1 = m01.w * SCALE;
        float v2 = m23.y * SCALE, v3 = m23.w * SCALE;
        float4 a0 = *(reinterpret_cast<const float4*>(x + (size_t)c0 * EMB) + lane);
        float4 a1 = *(reinterpret_cast<const float4*>(x + (size_t)c1 * EMB) + lane);
        float4 a2 = *(reinterpret_cast<const float4*>(x + (size_t)c2 * EMB) + lane);
        float4 a3 = *(reinterpret_cast<const float4*>(x + (size_t)c3 * EMB) + lane);
        acc.x += v0 * a0.x; acc.y += v0 * a0.y; acc.z += v0 * a0.z; acc.w += v0 * a0.w;
        acc.x += v1 * a1.x; acc.y += v1 * a1.y; acc.z += v1 * a1.z; acc.w += v1 * a1.w;
        acc.x += v2 * a2.x; acc.y += v2 * a2.y; acc.z += v2 * a2.z; acc.w += v2 * a2.w;
        acc.x += v3 * a3.x; acc.y += v3 * a3.y; acc.z += v3 * a3.z; acc.w += v3 * a3.w;
    }
    for (; j + 1 < deg; j += 2) {
        float4 m01 = *reinterpret_cast<const float4*>(ebase + j);
        int   c0 = __float_as_int(m01.x), c1 = __float_as_int(m01.z);
        float v0 = m01.y * SCALE, v1 = m01.w * SCALE;
        float4 a0 = *(reinterpret_cast<const float4*>(x + (size_t)c0 * EMB) + lane);
        float4 a1 = *(reinterpret_cast<const float4*>(x + (size_t)c1 * EMB) + lane);
        acc.x += v0 * a0.x; acc.y += v0 * a0.y; acc.z += v0 * a0.z; acc.w += v0 * a0.w;
        acc.x += v1 * a1.x; acc.y += v1 * a1.y; acc.z += v1 * a1.z; acc.w += v1 * a1.w;
    }
    if (j < deg) {
        float2 e0 = ebase[j];
        int   c0 = __float_as_int(e0.x);
        float v0 = e0.y * SCALE;
        float4 a0 = *(reinterpret_cast<const float4*>(x + (size_t)c0 * EMB) + lane);
        acc.x += v0 * a0.x; acc.y += v0 * a0.y; acc.z += v0 * a0.z; acc.w += v0 * a0.w;
    }

    reinterpret_cast<float4*>(out + (size_t)n * EMB)[lane] = acc;
}

extern "C" void kernel_launch(void* const* d_in, const int* in_sizes, int n_in,
                              void* d_out, int out_size) {
    // metadata order: t, x, e, hg_vals, hg_rows, hg_cols
    const float* x    = (const float*)d_in[1];
    const float* emb  = (const float*)d_in[2];
    const float* vals = (const float*)d_in[3];
    const int*   rows = (const int*)d_in[4];
    const int*   cols = (const int*)d_in[5];
    float* out = (float*)d_out;

    // Zero counters via memset node (graph-capturable, cheaper than a kernel)
    void* count_ptr = nullptr;
    cudaGetSymbolAddress(&count_ptr, g_count);
    cudaMemsetAsync(count_ptr, 0, N_NODES * sizeof(int));

    scatter_kernel<<<(N_EDGES / 4 + 255) / 256, 256>>>(vals, rows, cols);
    gather_kernel<<<(N_NODES * 32 + 255) / 256, 256>>>(x, emb, out);
}